// round 5
// baseline (speedup 1.0000x reference)
#include <cuda_runtime.h>
#include <cstdint>
#include <math.h>

// Problem constants
#define BDIM 4
#define SDIM 2048
#define DDIM 2048
#define HDIM 16
#define DKDIM 128
#define MDIM (BDIM * SDIM)   // 8192
#define GK 2048
#define GN 2048

#define NEGV (-1e9f)
#define SCALE 0.08838834764831845f  // 1/sqrt(128)

// Scratch (device globals — no cudaMalloc allowed)
__device__ float g_Q[(size_t)MDIM * DDIM];
__device__ float g_K[(size_t)MDIM * DDIM];
__device__ float g_V[(size_t)MDIM * DDIM];
__device__ float g_att[(size_t)MDIM * DDIM];
__device__ float g_vmean[BDIM * HDIM * DKDIM];

// ---------------------------------------------------------------------------
// Helpers
// ---------------------------------------------------------------------------
__device__ __forceinline__ void mma_bf16_16x8x16(
    float* c, const uint32_t* a, uint32_t b0, uint32_t b1)
{
    asm volatile(
        "mma.sync.aligned.m16n8k16.row.col.f32.bf16.bf16.f32 "
        "{%0,%1,%2,%3}, {%4,%5,%6,%7}, {%8,%9}, {%0,%1,%2,%3};"
        : "+f"(c[0]), "+f"(c[1]), "+f"(c[2]), "+f"(c[3])
        : "r"(a[0]), "r"(a[1]), "r"(a[2]), "r"(a[3]), "r"(b0), "r"(b1));
}

// Split a pair of fp32 into packed bf16 hi and packed bf16 lo (rn-even).
// hi = {bf16(x) | bf16(y)<<16}, lo = residuals in same packing.
__device__ __forceinline__ void split2(float x, float y, uint32_t& hi, uint32_t& lo)
{
    uint32_t bx = __float_as_uint(x), by = __float_as_uint(y);
    uint32_t hx = (bx + 0x7FFFu + ((bx >> 16) & 1u)) >> 16;
    uint32_t hy = (by + 0x7FFFu + ((by >> 16) & 1u)) >> 16;
    hi = hx | (hy << 16);
    float lx = x - __uint_as_float(hx << 16);
    float ly = y - __uint_as_float(hy << 16);
    uint32_t blx = __float_as_uint(lx), bly = __float_as_uint(ly);
    uint32_t hlx = (blx + 0x7FFFu + ((blx >> 16) & 1u)) >> 16;
    uint32_t hly = (bly + 0x7FFFu + ((bly >> 16) & 1u)) >> 16;
    lo = hlx | (hly << 16);
}

// Fast exp on FMA pipe (avoids MUFU floor). Rel err ~2e-6 for x <= 0.
__device__ __forceinline__ float fexp(float x)
{
    float t = x * 1.4426950408889634f;
    t = fmaxf(t, -126.0f);
    float n = rintf(t);
    float f = t - n;
    float p = 0.0013333558f;
    p = fmaf(p, f, 0.0096181291f);
    p = fmaf(p, f, 0.0555041087f);
    p = fmaf(p, f, 0.2402265070f);
    p = fmaf(p, f, 0.6931471806f);
    p = fmaf(p, f, 1.0f);
    int e = (int)n;
    return __uint_as_float((uint32_t)((e + 127) << 23)) * p;
}

// ===========================================================================
// GEMM (TN) via split-bf16 mma: C = A @ W.T with near-fp32 accuracy.
// CTA tile 128x128, 8 warps (4m x 2n), warp tile 32x64, K chunk 32.
// ===========================================================================
__global__ void __launch_bounds__(256, 2) gemm_mma_kernel(
    const float* __restrict__ A, const float* __restrict__ W, float* __restrict__ C)
{
    __shared__ uint32_t Ahs[128][20];
    __shared__ uint32_t Als[128][20];
    __shared__ uint32_t Bhs[128][20];
    __shared__ uint32_t Bls[128][20];

    const int tid  = threadIdx.x;
    const int lane = tid & 31;
    const int w    = tid >> 5;
    const int wm   = (w & 3) * 32;
    const int wn   = (w >> 2) * 64;
    const int gid  = lane >> 2;
    const int tig  = lane & 3;
    const int bm   = blockIdx.y * 128;
    const int bn   = blockIdx.x * 128;

    const int r0   = tid >> 3;        // 0..31
    const int c0f  = (tid & 7) * 4;   // float col base
    const int c0u  = (tid & 7) * 2;   // uint col base

    const float* Ap = A + (size_t)(bm + r0) * GK + c0f;
    const float* Wp = W + (size_t)(bn + r0) * GK + c0f;

    float acc[2][8][4];
#pragma unroll
    for (int mt = 0; mt < 2; mt++)
#pragma unroll
        for (int nt = 0; nt < 8; nt++)
#pragma unroll
            for (int q = 0; q < 4; q++) acc[mt][nt][q] = 0.f;

    for (int kc = 0; kc < GK / 32; kc++) {
        __syncthreads();
        const float* Ak = Ap + kc * 32;
        const float* Wk = Wp + kc * 32;
#pragma unroll
        for (int j = 0; j < 4; j++) {
            float4 a = *(const float4*)(Ak + (size_t)(32 * j) * GK);
            uint32_t h0, l0, h1, l1;
            split2(a.x, a.y, h0, l0); split2(a.z, a.w, h1, l1);
            *(uint2*)&Ahs[r0 + 32 * j][c0u] = make_uint2(h0, h1);
            *(uint2*)&Als[r0 + 32 * j][c0u] = make_uint2(l0, l1);
            float4 b = *(const float4*)(Wk + (size_t)(32 * j) * GK);
            split2(b.x, b.y, h0, l0); split2(b.z, b.w, h1, l1);
            *(uint2*)&Bhs[r0 + 32 * j][c0u] = make_uint2(h0, h1);
            *(uint2*)&Bls[r0 + 32 * j][c0u] = make_uint2(l0, l1);
        }
        __syncthreads();

#pragma unroll
        for (int ks = 0; ks < 2; ks++) {
            const int kb = ks * 8;
            uint32_t ah[2][4], al[2][4];
#pragma unroll
            for (int mt = 0; mt < 2; mt++) {
                const int rb = wm + mt * 16;
                ah[mt][0] = Ahs[rb + gid][kb + tig];
                ah[mt][1] = Ahs[rb + gid + 8][kb + tig];
                ah[mt][2] = Ahs[rb + gid][kb + tig + 4];
                ah[mt][3] = Ahs[rb + gid + 8][kb + tig + 4];
                al[mt][0] = Als[rb + gid][kb + tig];
                al[mt][1] = Als[rb + gid + 8][kb + tig];
                al[mt][2] = Als[rb + gid][kb + tig + 4];
                al[mt][3] = Als[rb + gid + 8][kb + tig + 4];
            }
#pragma unroll
            for (int nt = 0; nt < 8; nt++) {
                const int nb = wn + nt * 8 + gid;
                uint32_t bh0 = Bhs[nb][kb + tig], bh1 = Bhs[nb][kb + tig + 4];
                uint32_t bl0 = Bls[nb][kb + tig], bl1 = Bls[nb][kb + tig + 4];
                mma_bf16_16x8x16(acc[0][nt], ah[0], bh0, bh1);
                mma_bf16_16x8x16(acc[1][nt], ah[1], bh0, bh1);
                mma_bf16_16x8x16(acc[0][nt], ah[0], bl0, bl1);
                mma_bf16_16x8x16(acc[1][nt], ah[1], bl0, bl1);
                mma_bf16_16x8x16(acc[0][nt], al[0], bh0, bh1);
                mma_bf16_16x8x16(acc[1][nt], al[1], bh0, bh1);
            }
        }
    }

#pragma unroll
    for (int mt = 0; mt < 2; mt++) {
        const int row = bm + wm + mt * 16 + gid;
#pragma unroll
        for (int nt = 0; nt < 8; nt++) {
            const int col = bn + wn + nt * 8 + tig * 2;
            *(float2*)(C + (size_t)row * GN + col) =
                make_float2(acc[mt][nt][0], acc[mt][nt][1]);
            *(float2*)(C + (size_t)(row + 8) * GN + col) =
                make_float2(acc[mt][nt][2], acc[mt][nt][3]);
        }
    }
}

// ---------------------------------------------------------------------------
// Per-(b,h) mean of V over sequence. 64 blocks x 1024 threads, 8-way split.
// ---------------------------------------------------------------------------
__global__ void vmean_kernel(const float* __restrict__ Vg, float* __restrict__ vmean)
{
    __shared__ float red[8][128];
    int bh = blockIdx.x;
    int b = bh >> 4, h = bh & 15;
    int d = threadIdx.x & 127;
    int ch = threadIdx.x >> 7;       // 0..7
    const float* Vb = Vg + ((size_t)b * SDIM + ch * 256) * DDIM + h * DKDIM + d;
    float s = 0.f;
    for (int j = 0; j < 256; j++) s += Vb[(size_t)j * DDIM];
    red[ch][d] = s;
    __syncthreads();
    if (ch == 0) {
        float t = red[0][d] + red[1][d] + red[2][d] + red[3][d]
                + red[4][d] + red[5][d] + red[6][d] + red[7][d];
        vmean[bh * DKDIM + d] = t * (1.f / (float)SDIM);
    }
}

// ===========================================================================
// Flash attention via split-bf16 mma (3-term). Q-tile 64, key tiles 64, 8 warps.
// QK: warps 4m x 2n (warp 16q x 32k). PV: warps 4m x 2d (warp 16q x 64d).
// SMEM (u32 units):
//   Qfh [0,4096)      Q hi A-frags: [(mblk*8+ks)*32+lane] uint4
//   Qfl [4096,8192)
//   Khi [8192, +4352) K hi k-paired, [key][68]; reused for Pph [row][36] + Ppl
//   Klo [12544, +4352)
//   Vhi [16896, +4352) V hi k-paired, [kp][136]
//   Vlo [21248, +4352)
//   stats at 25600: rowm[64] rowl[64] rowc[64] pmx[128] pls[128] mask[64]
// ===========================================================================
#define QFH 0
#define QFL 4096
#define KHI 8192
#define KLO 12544
#define PPH 8192
#define PPL 10496
#define VHI 16896
#define VLO 21248
#define STT 25600
#define ATT_SMEM_U32 26112
#define ATT_SMEM_BYTES (ATT_SMEM_U32 * 4)

__global__ void __launch_bounds__(256, 2) attn_mma_kernel(
    const float* __restrict__ Qg, const float* __restrict__ Kg,
    const float* __restrict__ Vg, const int* __restrict__ mask,
    const float* __restrict__ vmean, float* __restrict__ Og)
{
    extern __shared__ uint32_t smu[];
    float* rowm = (float*)(smu + STT);        // [64]
    float* rowl = rowm + 64;                  // [64]
    float* rowc = rowl + 64;                  // [64]
    float* pmx  = rowc + 64;                  // [2][64]
    float* pls  = pmx + 128;                  // [2][64]
    int*   maskS = (int*)(pls + 128);         // [64]

    const int qt = blockIdx.x, h = blockIdx.y, b = blockIdx.z;
    const int tid = threadIdx.x, lane = tid & 31, w = tid >> 5;
    const int gid = lane >> 2, tig = lane & 3;
    const int wqm = (w & 3) * 16;
    const int wn  = w >> 2;
    const int wd  = (w >> 2) * 64;
    const int q0  = qt * 64;

    const size_t base = ((size_t)b * SDIM) * DDIM + (size_t)h * DKDIM;
    const float* Qb = Qg + base;
    const float* Kb = Kg + base;
    const float* Vb = Vg + base;
    const int* mb = mask + b * SDIM;

    // Stage Q rows (f32) into K region scratch (stride 132), then repack to frags
    {
        float* Qs = (float*)(smu + KHI);
        for (int i = tid; i < 2048; i += 256) {
            int r = i >> 5, c4 = (i & 31) * 4;
            *(float4*)&Qs[r * 132 + c4] =
                *(const float4*)(Qb + (size_t)(q0 + r) * DDIM + c4);
        }
        if (tid < 64) { rowm[tid] = -3.402823466e38f; rowl[tid] = 0.f; }
        __syncthreads();

        const int mblk = w & 3;
#pragma unroll
        for (int s = 0; s < 4; s++) {
            const int ks = (w >> 2) * 4 + s;
            const float* ra = &Qs[(mblk * 16 + gid) * 132 + ks * 16];
            const float* rb = &Qs[(mblk * 16 + gid + 8) * 132 + ks * 16];
            uint32_t h0, l0, h1, l1, h2, l2, h3, l3;
            split2(ra[2 * tig], ra[2 * tig + 1], h0, l0);
            split2(rb[2 * tig], rb[2 * tig + 1], h1, l1);
            split2(ra[8 + 2 * tig], ra[9 + 2 * tig], h2, l2);
            split2(rb[8 + 2 * tig], rb[9 + 2 * tig], h3, l3);
            uint32_t fo = (uint32_t)((mblk * 8 + ks) * 128 + lane * 4);
            *(uint4*)&smu[QFH + fo] = make_uint4(h0, h1, h2, h3);
            *(uint4*)&smu[QFL + fo] = make_uint4(l0, l1, l2, l3);
        }
    }

    const int r1 = wqm + gid, r2 = wqm + gid + 8;

    float o[8][4];
#pragma unroll
    for (int nt = 0; nt < 8; nt++)
#pragma unroll
        for (int q = 0; q < 4; q++) o[nt][q] = 0.f;

    for (int kt = 0; kt <= qt; kt++) {
        const int k0 = kt * 64;
        __syncthreads();  // prior smem reads (incl. Q repack reads) complete

        // K: [64 keys][128 d] -> hi/lo k-paired u32 [key][c], stride 68
        for (int i = tid; i < 2048; i += 256) {
            int r = i >> 5, c4 = (i & 31) * 4;
            float4 v = *(const float4*)(Kb + (size_t)(k0 + r) * DDIM + c4);
            uint32_t h0, l0, h1, l1;
            split2(v.x, v.y, h0, l0); split2(v.z, v.w, h1, l1);
            uint32_t off = (uint32_t)(r * 68 + c4 / 2);
            *(uint2*)&smu[KHI + off] = make_uint2(h0, h1);
            *(uint2*)&smu[KLO + off] = make_uint2(l0, l1);
        }
        // V: pack key-pairs: Vp[kp][d] = {V[2kp][d], V[2kp+1][d]}, stride 136
        for (int i = tid; i < 1024; i += 256) {
            int kp = i >> 5, d4 = (i & 31) * 4;
            float4 va = *(const float4*)(Vb + (size_t)(k0 + 2 * kp) * DDIM + d4);
            float4 vb2 = *(const float4*)(Vb + (size_t)(k0 + 2 * kp + 1) * DDIM + d4);
            uint32_t h0, l0, h1, l1, h2, l2, h3, l3;
            split2(va.x, vb2.x, h0, l0); split2(va.y, vb2.y, h1, l1);
            split2(va.z, vb2.z, h2, l2); split2(va.w, vb2.w, h3, l3);
            uint32_t off = (uint32_t)(kp * 136 + d4);
            *(uint4*)&smu[VHI + off] = make_uint4(h0, h1, h2, h3);
            *(uint4*)&smu[VLO + off] = make_uint4(l0, l1, l2, l3);
        }
        if (tid < 64) maskS[tid] = mb[k0 + tid];
        __syncthreads();

        // QK^T: 3-term split-bf16
        float sc[4][4];
#pragma unroll
        for (int nt = 0; nt < 4; nt++)
#pragma unroll
            for (int q = 0; q < 4; q++) sc[nt][q] = 0.f;

#pragma unroll
        for (int ks = 0; ks < 8; ks++) {
            uint32_t fo = (uint32_t)(((w & 3) * 8 + ks) * 128 + lane * 4);
            uint4 ahv = *(const uint4*)&smu[QFH + fo];
            uint4 alv = *(const uint4*)&smu[QFL + fo];
            uint32_t ah[4] = {ahv.x, ahv.y, ahv.z, ahv.w};
            uint32_t al[4] = {alv.x, alv.y, alv.z, alv.w};
#pragma unroll
            for (int nt = 0; nt < 4; nt++) {
                int key = wn * 32 + nt * 8 + gid;
                uint32_t kh0 = smu[KHI + key * 68 + ks * 8 + tig];
                uint32_t kh1 = smu[KHI + key * 68 + ks * 8 + 4 + tig];
                uint32_t kl0 = smu[KLO + key * 68 + ks * 8 + tig];
                uint32_t kl1 = smu[KLO + key * 68 + ks * 8 + 4 + tig];
                mma_bf16_16x8x16(sc[nt], ah, kh0, kh1);
                mma_bf16_16x8x16(sc[nt], ah, kl0, kl1);
                mma_bf16_16x8x16(sc[nt], al, kh0, kh1);
            }
        }

        // Mask + scale + per-row partial max
        float m1 = -3.402823466e38f, m2 = -3.402823466e38f;
#pragma unroll
        for (int nt = 0; nt < 4; nt++) {
#pragma unroll
            for (int jj = 0; jj < 2; jj++) {
                int jloc = wn * 32 + nt * 8 + tig * 2 + jj;
                int jg = k0 + jloc;
                bool ok = (maskS[jloc] != 0);
                float s0 = (ok && jg <= q0 + r1) ? sc[nt][jj] * SCALE : NEGV;
                float s1 = (ok && jg <= q0 + r2) ? sc[nt][2 + jj] * SCALE : NEGV;
                sc[nt][jj] = s0; sc[nt][2 + jj] = s1;
                m1 = fmaxf(m1, s0); m2 = fmaxf(m2, s1);
            }
        }
        m1 = fmaxf(m1, __shfl_xor_sync(0xffffffffu, m1, 1));
        m1 = fmaxf(m1, __shfl_xor_sync(0xffffffffu, m1, 2));
        m2 = fmaxf(m2, __shfl_xor_sync(0xffffffffu, m2, 1));
        m2 = fmaxf(m2, __shfl_xor_sync(0xffffffffu, m2, 2));
        if (tig == 0) { pmx[wn * 64 + r1] = m1; pmx[wn * 64 + r2] = m2; }
        __syncthreads();  // pmx ready; K reads done -> K region reusable for P

        float mn1 = fmaxf(rowm[r1], fmaxf(pmx[r1], pmx[64 + r1]));
        float mn2 = fmaxf(rowm[r2], fmaxf(pmx[r2], pmx[64 + r2]));
        float l1 = 0.f, l2 = 0.f;
#pragma unroll
        for (int nt = 0; nt < 4; nt++) {
            float p00 = fexp(sc[nt][0] - mn1), p01 = fexp(sc[nt][1] - mn1);
            float p10 = fexp(sc[nt][2] - mn2), p11 = fexp(sc[nt][3] - mn2);
            l1 += p00 + p01; l2 += p10 + p11;
            int cb = wn * 16 + nt * 4 + tig;  // packed col index (pairs)
            uint32_t hA, lA, hB, lB;
            split2(p00, p01, hA, lA);
            split2(p10, p11, hB, lB);
            smu[PPH + r1 * 36 + cb] = hA;
            smu[PPL + r1 * 36 + cb] = lA;
            smu[PPH + r2 * 36 + cb] = hB;
            smu[PPL + r2 * 36 + cb] = lB;
        }
        l1 += __shfl_xor_sync(0xffffffffu, l1, 1);
        l1 += __shfl_xor_sync(0xffffffffu, l1, 2);
        l2 += __shfl_xor_sync(0xffffffffu, l2, 1);
        l2 += __shfl_xor_sync(0xffffffffu, l2, 2);
        if (tig == 0) { pls[wn * 64 + r1] = l1; pls[wn * 64 + r2] = l2; }
        __syncthreads();  // pls + P stores visible

        if (tid < 64) {
            float mo = rowm[tid];
            float mn = fmaxf(mo, fmaxf(pmx[tid], pmx[64 + tid]));
            float corr = fexp(mo - mn);
            rowc[tid] = corr;
            rowm[tid] = mn;
            rowl[tid] = rowl[tid] * corr + pls[tid] + pls[64 + tid];
        }
        __syncthreads();  // rowc ready

        // PV: rescale, then 3-term split-bf16 accumulate
        float c1 = rowc[r1], c2 = rowc[r2];
#pragma unroll
        for (int nt = 0; nt < 8; nt++) {
            o[nt][0] *= c1; o[nt][1] *= c1; o[nt][2] *= c2; o[nt][3] *= c2;
        }
#pragma unroll
        for (int ks2 = 0; ks2 < 4; ks2++) {
            uint32_t ph[4], pl[4];
            ph[0] = smu[PPH + r1 * 36 + ks2 * 8 + tig];
            ph[1] = smu[PPH + r2 * 36 + ks2 * 8 + tig];
            ph[2] = smu[PPH + r1 * 36 + ks2 * 8 + 4 + tig];
            ph[3] = smu[PPH + r2 * 36 + ks2 * 8 + 4 + tig];
            pl[0] = smu[PPL + r1 * 36 + ks2 * 8 + tig];
            pl[1] = smu[PPL + r2 * 36 + ks2 * 8 + tig];
            pl[2] = smu[PPL + r1 * 36 + ks2 * 8 + 4 + tig];
            pl[3] = smu[PPL + r2 * 36 + ks2 * 8 + 4 + tig];
#pragma unroll
            for (int nt = 0; nt < 8; nt++) {
                int d = wd + nt * 8 + gid;
                uint32_t vh0 = smu[VHI + (ks2 * 8 + tig) * 136 + d];
                uint32_t vh1 = smu[VHI + (ks2 * 8 + 4 + tig) * 136 + d];
                uint32_t vl0 = smu[VLO + (ks2 * 8 + tig) * 136 + d];
                uint32_t vl1 = smu[VLO + (ks2 * 8 + 4 + tig) * 136 + d];
                mma_bf16_16x8x16(o[nt], ph, vh0, vh1);
                mma_bf16_16x8x16(o[nt], ph, vl0, vl1);
                mma_bf16_16x8x16(o[nt], pl, vh0, vh1);
            }
        }
    }

    // Epilogue
    float inv1 = 1.f / rowl[r1], inv2 = 1.f / rowl[r2];
    bool dead1 = rowm[r1] < -1e8f, dead2 = rowm[r2] < -1e8f;
    const float* vm = vmean + ((size_t)b * HDIM + h) * DKDIM;
    float* O1 = Og + ((size_t)b * SDIM + q0 + r1) * DDIM + h * DKDIM;
    float* O2 = Og + ((size_t)b * SDIM + q0 + r2) * DDIM + h * DKDIM;
#pragma unroll
    for (int nt = 0; nt < 8; nt++) {
        int d = wd + nt * 8 + tig * 2;
        float2 u1 = dead1 ? make_float2(vm[d], vm[d + 1])
                          : make_float2(o[nt][0] * inv1, o[nt][1] * inv1);
        float2 u2 = dead2 ? make_float2(vm[d], vm[d + 1])
                          : make_float2(o[nt][2] * inv2, o[nt][3] * inv2);
        *(float2*)(O1 + d) = u1;
        *(float2*)(O2 + d) = u2;
    }
}

// ---------------------------------------------------------------------------
extern "C" void kernel_launch(void* const* d_in, const int* in_sizes, int n_in,
                              void* d_out, int out_size)
{
    const float* x    = (const float*)d_in[0];
    const int*   mask = (const int*)d_in[1];
    const float* wq   = (const float*)d_in[2];
    const float* wk   = (const float*)d_in[3];
    const float* wv   = (const float*)d_in[4];
    const float* wo   = (const float*)d_in[5];
    float* out = (float*)d_out;

    float *pQ, *pK, *pV, *pAtt, *pVm;
    cudaGetSymbolAddress((void**)&pQ, g_Q);
    cudaGetSymbolAddress((void**)&pK, g_K);
    cudaGetSymbolAddress((void**)&pV, g_V);
    cudaGetSymbolAddress((void**)&pAtt, g_att);
    cudaGetSymbolAddress((void**)&pVm, g_vmean);

    cudaFuncSetAttribute(attn_mma_kernel, cudaFuncAttributeMaxDynamicSharedMemorySize,
                         ATT_SMEM_BYTES);

    dim3 gg(GN / 128, MDIM / 128);  // (16, 64)
    gemm_mma_kernel<<<gg, 256>>>(x, wq, pQ);
    gemm_mma_kernel<<<gg, 256>>>(x, wk, pK);
    gemm_mma_kernel<<<gg, 256>>>(x, wv, pV);

    vmean_kernel<<<BDIM * HDIM, 1024>>>(pV, pVm);

    attn_mma_kernel<<<dim3(SDIM / 64, HDIM, BDIM), 256, ATT_SMEM_BYTES>>>(
        pQ, pK, pV, mask, pVm, pAtt);

    gemm_mma_kernel<<<gg, 256>>>(pAtt, wo, out);
}